// round 5
// baseline (speedup 1.0000x reference)
#include <cuda_runtime.h>
#include <cuda_bf16.h>
#include <math.h>
#include <stdint.h>

#define Nn 50000
#define Ee 1600000
#define Hh 128
#define NUc 49232
#define NMc 512
#define NSc 256
#define NB 196   // ceil(Nn/256)

// ---------------- scratch (static device globals; no allocation) ----------------
__device__ float g_hm[(size_t)Nn * Hh];   // GEMM output (pre-aggregation), reused per layer
__device__ float g_ha[(size_t)Nn * Hh];   // ping (agg output)
__device__ float g_hb[(size_t)Nn * Hh];   // pong
__device__ float g_el[Nn];
__device__ float g_er[Nn];
__device__ int   g_cnt[Nn];
__device__ int   g_rowptr[Nn + 1];
__device__ int   g_cursor[Nn];
__device__ int   g_ssrc[Ee];
__device__ float g_T[NMc * Hh];
__device__ int   g_bsum[NB];
__device__ int   g_boff[NB];

// ---------------- CSR build ----------------
__global__ void zero_cnt_kernel() {
    int i = blockIdx.x * blockDim.x + threadIdx.x;
    if (i < Nn) g_cnt[i] = 0;
}

__global__ void hist_kernel(const int* __restrict__ dst) {
    int stride = gridDim.x * blockDim.x;
#pragma unroll 4
    for (int i = blockIdx.x * blockDim.x + threadIdx.x; i < Ee; i += stride)
        atomicAdd(&g_cnt[dst[i]], 1);
}

__global__ void scanA_kernel() {
    __shared__ int ws[8];
    int t = threadIdx.x, lane = t & 31, warp = t >> 5;
    int i = blockIdx.x * 256 + t;
    int v = (i < Nn) ? g_cnt[i] : 0;
    int x = v;
#pragma unroll
    for (int o = 16; o; o >>= 1) x += __shfl_xor_sync(0xffffffffu, x, o);
    if (lane == 0) ws[warp] = x;
    __syncthreads();
    if (t == 0) {
        int s = 0;
#pragma unroll
        for (int w = 0; w < 8; ++w) s += ws[w];
        g_bsum[blockIdx.x] = s;
    }
}

__global__ void scanB_kernel() {
    __shared__ int s[256];
    int t = threadIdx.x;
    s[t] = (t < NB) ? g_bsum[t] : 0;
    __syncthreads();
#pragma unroll
    for (int off = 1; off < 256; off <<= 1) {
        int v = (t >= off) ? s[t - off] : 0;
        __syncthreads();
        s[t] += v;
        __syncthreads();
    }
    if (t < NB) g_boff[t] = s[t] - g_bsum[t];
    if (t == 0) g_rowptr[Nn] = Ee;
}

__global__ void scanC_kernel() {
    __shared__ int s[256];
    int t = threadIdx.x;
    int i = blockIdx.x * 256 + t;
    int v = (i < Nn) ? g_cnt[i] : 0;
    s[t] = v;
    __syncthreads();
#pragma unroll
    for (int off = 1; off < 256; off <<= 1) {
        int q = (t >= off) ? s[t - off] : 0;
        __syncthreads();
        s[t] += q;
        __syncthreads();
    }
    if (i < Nn) {
        int excl = s[t] - v + g_boff[blockIdx.x];
        g_rowptr[i] = excl;
        g_cursor[i] = excl;
    }
}

__global__ void scatter_kernel(const int* __restrict__ src, const int* __restrict__ dst) {
    int stride = gridDim.x * blockDim.x;
#pragma unroll 4
    for (int i = blockIdx.x * blockDim.x + threadIdx.x; i < Ee; i += stride) {
        int d = dst[i];
        int p = atomicAdd(&g_cursor[d], 1);
        g_ssrc[p] = src[i];
    }
}

// ---------------- tf32 tensor-core GEMM, error-compensated (hi tf32, lo bf16) ----------
__device__ __forceinline__ uint32_t f2tf32(float x) {
    uint32_t r;
    asm("cvt.rna.tf32.f32 %0, %1;" : "=r"(r) : "f"(x));
    return r;
}
__device__ __forceinline__ void mma_tf32(float c[4], const uint32_t a[4], uint32_t b0, uint32_t b1) {
    asm volatile(
        "mma.sync.aligned.m16n8k8.row.col.f32.tf32.tf32.f32 "
        "{%0,%1,%2,%3}, {%4,%5,%6,%7}, {%8,%9}, {%0,%1,%2,%3};"
        : "+f"(c[0]), "+f"(c[1]), "+f"(c[2]), "+f"(c[3])
        : "r"(a[0]), "r"(a[1]), "r"(a[2]), "r"(a[3]), "r"(b0), "r"(b1));
}

#define WPAD 136
#define WPADH 272

__global__ void gemm_tf32_kernel(const float* __restrict__ X, const float* __restrict__ W,
                                 const float* __restrict__ al, const float* __restrict__ ar,
                                 float* __restrict__ Hout, int nrows, int compute_elr) {
    extern __shared__ float smem[];                     // Whi[128][136] fp32 | Wlo[128][272] bf16
    float* Whi = smem;
    __nv_bfloat16* Wlo = (__nv_bfloat16*)(smem + 128 * WPAD);

    for (int i = threadIdx.x; i < Hh * Hh; i += blockDim.x) {
        int k = i >> 7, n = i & 127;
        float w = W[i];
        uint32_t hb = f2tf32(w);
        float hf = __uint_as_float(hb);
        Whi[k * WPAD + n] = hf;
        Wlo[k * WPADH + n] = __float2bfloat16(w - hf);
    }
    __syncthreads();

    const unsigned FULL = 0xffffffffu;
    int lane = threadIdx.x & 31;
    int warp = threadIdx.x >> 5;
    int g = lane >> 2, tig = lane & 3;
    int gw = blockIdx.x * (blockDim.x >> 5) + warp;
    int nwarps = gridDim.x * (blockDim.x >> 5);
    int ngroups = (nrows + 15) >> 4;

    for (int grp = gw; grp < ngroups; grp += nwarps) {
        int row0 = grp * 16;
        int rA = row0 + g, rB = row0 + g + 8;
        bool vA = rA < nrows, vB = rB < nrows;

        float c[16][4];
#pragma unroll
        for (int nt = 0; nt < 16; ++nt) {
            c[nt][0] = 0.f; c[nt][1] = 0.f; c[nt][2] = 0.f; c[nt][3] = 0.f;
        }

#pragma unroll 2
        for (int kt = 0; kt < 16; ++kt) {
            int k0 = kt * 8;
            float af[4];
            af[0] = vA ? X[(size_t)rA * Hh + k0 + tig]     : 0.f;
            af[1] = vB ? X[(size_t)rB * Hh + k0 + tig]     : 0.f;
            af[2] = vA ? X[(size_t)rA * Hh + k0 + tig + 4] : 0.f;
            af[3] = vB ? X[(size_t)rB * Hh + k0 + tig + 4] : 0.f;
            uint32_t ahi[4], alo[4];
#pragma unroll
            for (int q = 0; q < 4; ++q) {
                ahi[q] = f2tf32(af[q]);
                alo[q] = f2tf32(af[q] - __uint_as_float(ahi[q]));
            }
#pragma unroll
            for (int nt = 0; nt < 16; ++nt) {
                int n0 = nt * 8;
                uint32_t bh0 = __float_as_uint(Whi[(k0 + tig) * WPAD + n0 + g]);
                uint32_t bh1 = __float_as_uint(Whi[(k0 + tig + 4) * WPAD + n0 + g]);
                uint32_t bl0 = f2tf32(__bfloat162float(Wlo[(k0 + tig) * WPADH + n0 + g]));
                uint32_t bl1 = f2tf32(__bfloat162float(Wlo[(k0 + tig + 4) * WPADH + n0 + g]));
                mma_tf32(c[nt], ahi, bh0, bh1);   // hi*hi
                mma_tf32(c[nt], ahi, bl0, bl1);   // hi*lo
                mma_tf32(c[nt], alo, bh0, bh1);   // lo*hi
            }
        }

        float pal = 0.f, par = 0.f, pbl = 0.f, pbr = 0.f;
#pragma unroll
        for (int nt = 0; nt < 16; ++nt) {
            int col = nt * 8 + 2 * tig;
            if (vA) *(float2*)&Hout[(size_t)rA * Hh + col] = make_float2(c[nt][0], c[nt][1]);
            if (vB) *(float2*)&Hout[(size_t)rB * Hh + col] = make_float2(c[nt][2], c[nt][3]);
            if (compute_elr) {
                float a0 = al[col], a1 = al[col + 1];
                float r0v = ar[col], r1v = ar[col + 1];
                pal += c[nt][0] * a0 + c[nt][1] * a1;
                par += c[nt][0] * r0v + c[nt][1] * r1v;
                pbl += c[nt][2] * a0 + c[nt][3] * a1;
                pbr += c[nt][2] * r0v + c[nt][3] * r1v;
            }
        }
        if (compute_elr) {
#pragma unroll
            for (int o = 1; o < 4; o <<= 1) {
                pal += __shfl_xor_sync(FULL, pal, o);
                par += __shfl_xor_sync(FULL, par, o);
                pbl += __shfl_xor_sync(FULL, pbl, o);
                pbr += __shfl_xor_sync(FULL, pbr, o);
            }
            if (tig == 0) {
                if (vA) { g_el[rA] = pal; g_er[rA] = par; }
                if (vB) { g_el[rB] = pbl; g_er[rB] = pbr; }
            }
        }
    }
}

// ---------------- fused edge softmax + aggregation: 4 warps per dst node ----------------
__global__ void agg_kernel(const float* __restrict__ h, const float* __restrict__ bias,
                           float* __restrict__ hout, int do_relu) {
    __shared__ float sacc[2][4][Hh];   // [node_in_block][warp_in_node][dim]
    __shared__ float ssum[2][4];

    int tid = threadIdx.x;
    int lane = tid & 31;
    int warp = tid >> 5;           // 0..7
    int nib = warp >> 2;           // node within block: 0..1
    int win = warp & 3;            // warp within node: 0..3
    int v = blockIdx.x * 2 + nib;  // grid = 25000 -> v < 50000 always

    int r0 = g_rowptr[v];
    int r1 = g_rowptr[v + 1];
    float elv = g_el[v];

    float4 acc = make_float4(0.f, 0.f, 0.f, 0.f);
    float s = 0.f;
#pragma unroll 4
    for (int i = r0 + win; i < r1; i += 4) {
        int sv = g_ssrc[i];
        float e = elv + g_er[sv];
        e = e > 0.f ? e : 0.2f * e;
        float w = __expf(e);
        s += w;
        float4 hv = *(const float4*)(h + (size_t)sv * Hh + lane * 4);
        acc.x += w * hv.x;
        acc.y += w * hv.y;
        acc.z += w * hv.z;
        acc.w += w * hv.w;
    }
    ((float4*)sacc[nib][win])[lane] = acc;
    if (lane == 0) ssum[nib][win] = s;
    __syncthreads();

    if (win == 0) {
        float4 a0 = ((float4*)sacc[nib][0])[lane];
        float4 a1 = ((float4*)sacc[nib][1])[lane];
        float4 a2 = ((float4*)sacc[nib][2])[lane];
        float4 a3 = ((float4*)sacc[nib][3])[lane];
        float st = ssum[nib][0] + ssum[nib][1] + ssum[nib][2] + ssum[nib][3];
        float inv = 1.f / (st + 1e-10f);
        float4 bv = *(const float4*)(bias + lane * 4);
        float4 o;
        o.x = (a0.x + a1.x + a2.x + a3.x) * inv + bv.x;
        o.y = (a0.y + a1.y + a2.y + a3.y) * inv + bv.y;
        o.z = (a0.z + a1.z + a2.z + a3.z) * inv + bv.z;
        o.w = (a0.w + a1.w + a2.w + a3.w) * inv + bv.w;
        if (do_relu) {
            o.x = fmaxf(o.x, 0.f);
            o.y = fmaxf(o.y, 0.f);
            o.z = fmaxf(o.z, 0.f);
            o.w = fmaxf(o.w, 0.f);
        }
        *(float4*)(hout + (size_t)v * Hh + lane * 4) = o;
    }
}

// ---------------- scores = T @ server^T + bb ----------------
__global__ void scores_kernel(const float* __restrict__ Tm, const float* __restrict__ S,
                              const float* __restrict__ bb, float* __restrict__ out) {
    const unsigned FULL = 0xffffffffu;
    int lane = threadIdx.x & 31;
    int w = (blockIdx.x * blockDim.x + threadIdx.x) >> 5;
    if (w >= NMc * 8) return;
    int m = w >> 3;
    int sbase = (w & 7) * 32;
    float4 t = ((const float4*)(Tm + (size_t)m * Hh))[lane];
    float b = bb[0];
    for (int j = 0; j < 32; ++j) {
        int sidx = sbase + j;
        float4 sv = ((const float4*)(S + (size_t)sidx * Hh))[lane];
        float d = t.x * sv.x + t.y * sv.y + t.z * sv.z + t.w * sv.w;
#pragma unroll
        for (int o = 16; o; o >>= 1) d += __shfl_xor_sync(FULL, d, o);
        if (lane == 0) out[m * NSc + sidx] = d + b;
    }
}

// ---------------- launch ----------------
extern "C" void kernel_launch(void* const* d_in, const int* in_sizes, int n_in,
                              void* d_out, int out_size) {
    (void)in_sizes; (void)n_in; (void)out_size;
    const float* x   = (const float*)d_in[0];
    const int*   ei  = (const int*)d_in[1];
    const float* W1  = (const float*)d_in[2];
    const float* al1 = (const float*)d_in[3];
    const float* ar1 = (const float*)d_in[4];
    const float* b1  = (const float*)d_in[5];
    const float* W2  = (const float*)d_in[6];
    const float* al2 = (const float*)d_in[7];
    const float* ar2 = (const float*)d_in[8];
    const float* b2  = (const float*)d_in[9];
    const float* W3  = (const float*)d_in[10];
    const float* al3 = (const float*)d_in[11];
    const float* ar3 = (const float*)d_in[12];
    const float* b3  = (const float*)d_in[13];
    const float* Wb  = (const float*)d_in[14];
    const float* bb  = (const float*)d_in[15];
    float* out = (float*)d_out;

    const int* src = ei;
    const int* dst = ei + Ee;

    const int SMEM_GEMM = 128 * WPAD * 4 + 128 * WPADH * 2;   // 139264 B
    cudaFuncSetAttribute(gemm_tf32_kernel, cudaFuncAttributeMaxDynamicSharedMemorySize, SMEM_GEMM);

    float *hm, *ha, *hb, *Tp;
    cudaGetSymbolAddress((void**)&hm, g_hm);
    cudaGetSymbolAddress((void**)&ha, g_ha);
    cudaGetSymbolAddress((void**)&hb, g_hb);
    cudaGetSymbolAddress((void**)&Tp, g_T);

    const int GEMM_GRID = 391;
    const int AGG_GRID  = Nn / 2;   // 2 nodes per 256-thread block

    // CSR build interleaved with layer-1 GEMM (gemm1 independent of CSR).
    // Launch #4 = gemm1 -> ncu profile slot.
    zero_cnt_kernel<<<NB, 256>>>();                                            // 1
    hist_kernel<<<2048, 256>>>(dst);                                           // 2
    scanA_kernel<<<NB, 256>>>();                                               // 3
    gemm_tf32_kernel<<<GEMM_GRID, 256, SMEM_GEMM>>>(x, W1, al1, ar1, hm, Nn, 1); // 4 (profiled)
    scanB_kernel<<<1, 256>>>();                                                // 5
    scanC_kernel<<<NB, 256>>>();                                               // 6
    scatter_kernel<<<2048, 256>>>(src, dst);                                   // 7

    // layer 1 aggregation
    agg_kernel<<<AGG_GRID, 256>>>(hm, b1, ha, 1);
    // layer 2
    gemm_tf32_kernel<<<GEMM_GRID, 256, SMEM_GEMM>>>(ha, W2, al2, ar2, hm, Nn, 1);
    agg_kernel<<<AGG_GRID, 256>>>(hm, b2, hb, 1);
    // layer 3
    gemm_tf32_kernel<<<GEMM_GRID, 256, SMEM_GEMM>>>(hb, W3, al3, ar3, hm, Nn, 1);
    agg_kernel<<<AGG_GRID, 256>>>(hm, b3, ha, 0);

    // bilinear head
    gemm_tf32_kernel<<<4, 256, SMEM_GEMM>>>(ha + (size_t)NUc * Hh, Wb, al1, ar1, Tp, NMc, 0);
    scores_kernel<<<512, 256>>>(Tp, ha + (size_t)(NUc + NMc) * Hh, bb, out);
}

// round 6
// speedup vs baseline: 1.0877x; 1.0877x over previous
#include <cuda_runtime.h>
#include <cuda_bf16.h>
#include <math.h>
#include <stdint.h>

#define Nn 50000
#define Ee 1600000
#define Hh 128
#define NUc 49232
#define NMc 512
#define NSc 256
#define NB 196   // ceil(Nn/256)

// ---------------- scratch (static device globals; no allocation) ----------------
__device__ float g_hm[(size_t)Nn * Hh];   // GEMM output (pre-aggregation), reused per layer
__device__ float g_ha[(size_t)Nn * Hh];   // ping (agg output)
__device__ float g_hb[(size_t)Nn * Hh];   // pong
__device__ float g_el[Nn];
__device__ float g_er[Nn];
__device__ int   g_cnt[Nn];
__device__ int   g_rowptr[Nn + 1];
__device__ int   g_cursor[Nn];
__device__ int   g_ssrc[Ee];
__device__ float g_T[NMc * Hh];
__device__ int   g_bsum[NB];
__device__ int   g_boff[NB];

// ---------------- CSR build ----------------
__global__ void zero_cnt_kernel() {
    int i = blockIdx.x * blockDim.x + threadIdx.x;
    if (i < Nn) g_cnt[i] = 0;
}

__global__ void hist_kernel(const int* __restrict__ dst) {
    int stride = gridDim.x * blockDim.x;
#pragma unroll 4
    for (int i = blockIdx.x * blockDim.x + threadIdx.x; i < Ee; i += stride)
        atomicAdd(&g_cnt[dst[i]], 1);
}

__global__ void scanA_kernel() {
    __shared__ int ws[8];
    int t = threadIdx.x, lane = t & 31, warp = t >> 5;
    int i = blockIdx.x * 256 + t;
    int v = (i < Nn) ? g_cnt[i] : 0;
    int x = v;
#pragma unroll
    for (int o = 16; o; o >>= 1) x += __shfl_xor_sync(0xffffffffu, x, o);
    if (lane == 0) ws[warp] = x;
    __syncthreads();
    if (t == 0) {
        int s = 0;
#pragma unroll
        for (int w = 0; w < 8; ++w) s += ws[w];
        g_bsum[blockIdx.x] = s;
    }
}

__global__ void scanB_kernel() {
    __shared__ int s[256];
    int t = threadIdx.x;
    s[t] = (t < NB) ? g_bsum[t] : 0;
    __syncthreads();
#pragma unroll
    for (int off = 1; off < 256; off <<= 1) {
        int v = (t >= off) ? s[t - off] : 0;
        __syncthreads();
        s[t] += v;
        __syncthreads();
    }
    if (t < NB) g_boff[t] = s[t] - g_bsum[t];
    if (t == 0) g_rowptr[Nn] = Ee;
}

__global__ void scanC_kernel() {
    __shared__ int s[256];
    int t = threadIdx.x;
    int i = blockIdx.x * 256 + t;
    int v = (i < Nn) ? g_cnt[i] : 0;
    s[t] = v;
    __syncthreads();
#pragma unroll
    for (int off = 1; off < 256; off <<= 1) {
        int q = (t >= off) ? s[t - off] : 0;
        __syncthreads();
        s[t] += q;
        __syncthreads();
    }
    if (i < Nn) {
        int excl = s[t] - v + g_boff[blockIdx.x];
        g_rowptr[i] = excl;
        g_cursor[i] = excl;
    }
}

__global__ void scatter_kernel(const int* __restrict__ src, const int* __restrict__ dst) {
    int stride = gridDim.x * blockDim.x;
#pragma unroll 4
    for (int i = blockIdx.x * blockDim.x + threadIdx.x; i < Ee; i += stride) {
        int d = dst[i];
        int p = atomicAdd(&g_cursor[d], 1);
        g_ssrc[p] = src[i];
    }
}

// ---------------- tf32 tensor-core GEMM, error-compensated (hi tf32 fp32-smem, lo bf16-smem) ----------
__device__ __forceinline__ uint32_t f2tf32(float x) {
    uint32_t r;
    asm("cvt.rna.tf32.f32 %0, %1;" : "=r"(r) : "f"(x));
    return r;
}
__device__ __forceinline__ void mma_tf32(float c[4], const uint32_t a[4], uint32_t b0, uint32_t b1) {
    asm volatile(
        "mma.sync.aligned.m16n8k8.row.col.f32.tf32.tf32.f32 "
        "{%0,%1,%2,%3}, {%4,%5,%6,%7}, {%8,%9}, {%0,%1,%2,%3};"
        : "+f"(c[0]), "+f"(c[1]), "+f"(c[2]), "+f"(c[3])
        : "r"(a[0]), "r"(a[1]), "r"(a[2]), "r"(a[3]), "r"(b0), "r"(b1));
}

#define WPAD 136

__global__ __launch_bounds__(256, 2)
void gemm_tf32_kernel(const float* __restrict__ X, const float* __restrict__ W,
                      const float* __restrict__ al, const float* __restrict__ ar,
                      float* __restrict__ Hout, int nrows, int compute_elr) {
    extern __shared__ float smem[];                 // Whi[128][136] fp32 | Wlo[128][136] bf16
    float* Whi = smem;
    uint16_t* Wlo = (uint16_t*)(smem + 128 * WPAD);

    for (int i = threadIdx.x; i < Hh * Hh; i += blockDim.x) {
        int k = i >> 7, n = i & 127;
        float w = W[i];
        uint32_t hb = f2tf32(w);
        float hf = __uint_as_float(hb);
        Whi[k * WPAD + n] = hf;
        // bf16 is exactly representable in tf32: store raw bits, reload via <<16
        Wlo[k * WPAD + n] = (uint16_t)(__bfloat16_as_ushort(__float2bfloat16(w - hf)));
    }
    __syncthreads();

    const unsigned FULL = 0xffffffffu;
    int lane = threadIdx.x & 31;
    int warp = threadIdx.x >> 5;
    int g = lane >> 2, tig = lane & 3;
    int gw = blockIdx.x * (blockDim.x >> 5) + warp;
    int nwarps = gridDim.x * (blockDim.x >> 5);
    int ngroups = (nrows + 15) >> 4;

    for (int grp = gw; grp < ngroups; grp += nwarps) {
        int row0 = grp * 16;
        int rA = row0 + g, rB = row0 + g + 8;
        bool vA = rA < nrows, vB = rB < nrows;

        float c[16][4];
#pragma unroll
        for (int nt = 0; nt < 16; ++nt) {
            c[nt][0] = 0.f; c[nt][1] = 0.f; c[nt][2] = 0.f; c[nt][3] = 0.f;
        }

#pragma unroll 2
        for (int kt = 0; kt < 16; ++kt) {
            int k0 = kt * 8;
            float af[4];
            af[0] = vA ? X[(size_t)rA * Hh + k0 + tig]     : 0.f;
            af[1] = vB ? X[(size_t)rB * Hh + k0 + tig]     : 0.f;
            af[2] = vA ? X[(size_t)rA * Hh + k0 + tig + 4] : 0.f;
            af[3] = vB ? X[(size_t)rB * Hh + k0 + tig + 4] : 0.f;
            uint32_t ahi[4], alo[4];
#pragma unroll
            for (int q = 0; q < 4; ++q) {
                ahi[q] = f2tf32(af[q]);
                alo[q] = f2tf32(af[q] - __uint_as_float(ahi[q]));
            }
#pragma unroll
            for (int nt = 0; nt < 16; ++nt) {
                int n0 = nt * 8;
                uint32_t bh0 = __float_as_uint(Whi[(k0 + tig) * WPAD + n0 + g]);
                uint32_t bh1 = __float_as_uint(Whi[(k0 + tig + 4) * WPAD + n0 + g]);
                uint32_t bl0 = ((uint32_t)Wlo[(k0 + tig) * WPAD + n0 + g]) << 16;
                uint32_t bl1 = ((uint32_t)Wlo[(k0 + tig + 4) * WPAD + n0 + g]) << 16;
                mma_tf32(c[nt], ahi, bh0, bh1);   // hi*hi
                mma_tf32(c[nt], ahi, bl0, bl1);   // hi*lo
                mma_tf32(c[nt], alo, bh0, bh1);   // lo*hi
            }
        }

        float pal = 0.f, par = 0.f, pbl = 0.f, pbr = 0.f;
#pragma unroll
        for (int nt = 0; nt < 16; ++nt) {
            int col = nt * 8 + 2 * tig;
            if (vA) *(float2*)&Hout[(size_t)rA * Hh + col] = make_float2(c[nt][0], c[nt][1]);
            if (vB) *(float2*)&Hout[(size_t)rB * Hh + col] = make_float2(c[nt][2], c[nt][3]);
            if (compute_elr) {
                float a0 = al[col], a1 = al[col + 1];
                float r0v = ar[col], r1v = ar[col + 1];
                pal += c[nt][0] * a0 + c[nt][1] * a1;
                par += c[nt][0] * r0v + c[nt][1] * r1v;
                pbl += c[nt][2] * a0 + c[nt][3] * a1;
                pbr += c[nt][2] * r0v + c[nt][3] * r1v;
            }
        }
        if (compute_elr) {
#pragma unroll
            for (int o = 1; o < 4; o <<= 1) {
                pal += __shfl_xor_sync(FULL, pal, o);
                par += __shfl_xor_sync(FULL, par, o);
                pbl += __shfl_xor_sync(FULL, pbl, o);
                pbr += __shfl_xor_sync(FULL, pbr, o);
            }
            if (tig == 0) {
                if (vA) { g_el[rA] = pal; g_er[rA] = par; }
                if (vB) { g_el[rB] = pbl; g_er[rB] = pbr; }
            }
        }
    }
}

// ---------------- fused edge softmax + aggregation (warp per node, lane-parallel exp) ----------------
__global__ void agg_kernel(const float* __restrict__ h, const float* __restrict__ bias,
                           float* __restrict__ hout, int do_relu) {
    const unsigned FULL = 0xffffffffu;
    int lane = threadIdx.x & 31;
    int v = (blockIdx.x * blockDim.x + threadIdx.x) >> 5;
    if (v >= Nn) return;

    int r0 = g_rowptr[v];
    int r1 = g_rowptr[v + 1];
    float elv = g_el[v];

    float4 acc = make_float4(0.f, 0.f, 0.f, 0.f);
    float s = 0.f;
    for (int base = r0; base < r1; base += 32) {
        int i = base + lane;
        float w = 0.f;
        int sv = 0;
        if (i < r1) {
            sv = g_ssrc[i];                      // coalesced
            float e = elv + g_er[sv];
            e = e > 0.f ? e : 0.2f * e;
            w = __expf(e);                       // one exp warp-op per 32 edges
        }
        s += w;
        int cnt = min(32, r1 - base);
#pragma unroll 4
        for (int j = 0; j < cnt; ++j) {
            float wj = __shfl_sync(FULL, w, j);
            int svj = __shfl_sync(FULL, sv, j);
            float4 hv = *(const float4*)(h + (size_t)svj * Hh + lane * 4);
            acc.x += wj * hv.x;
            acc.y += wj * hv.y;
            acc.z += wj * hv.z;
            acc.w += wj * hv.w;
        }
    }
#pragma unroll
    for (int o = 16; o; o >>= 1) s += __shfl_xor_sync(FULL, s, o);

    float inv = 1.f / (s + 1e-10f);
    float4 bv = *(const float4*)(bias + lane * 4);
    float4 o;
    o.x = acc.x * inv + bv.x;
    o.y = acc.y * inv + bv.y;
    o.z = acc.z * inv + bv.z;
    o.w = acc.w * inv + bv.w;
    if (do_relu) {
        o.x = fmaxf(o.x, 0.f);
        o.y = fmaxf(o.y, 0.f);
        o.z = fmaxf(o.z, 0.f);
        o.w = fmaxf(o.w, 0.f);
    }
    *(float4*)(hout + (size_t)v * Hh + lane * 4) = o;
}

// ---------------- scores = T @ server^T + bb ----------------
__global__ void scores_kernel(const float* __restrict__ Tm, const float* __restrict__ S,
                              const float* __restrict__ bb, float* __restrict__ out) {
    const unsigned FULL = 0xffffffffu;
    int lane = threadIdx.x & 31;
    int w = (blockIdx.x * blockDim.x + threadIdx.x) >> 5;
    if (w >= NMc * 8) return;
    int m = w >> 3;
    int sbase = (w & 7) * 32;
    float4 t = ((const float4*)(Tm + (size_t)m * Hh))[lane];
    float b = bb[0];
    for (int j = 0; j < 32; ++j) {
        int sidx = sbase + j;
        float4 sv = ((const float4*)(S + (size_t)sidx * Hh))[lane];
        float d = t.x * sv.x + t.y * sv.y + t.z * sv.z + t.w * sv.w;
#pragma unroll
        for (int o = 16; o; o >>= 1) d += __shfl_xor_sync(FULL, d, o);
        if (lane == 0) out[m * NSc + sidx] = d + b;
    }
}

// ---------------- launch ----------------
extern "C" void kernel_launch(void* const* d_in, const int* in_sizes, int n_in,
                              void* d_out, int out_size) {
    (void)in_sizes; (void)n_in; (void)out_size;
    const float* x   = (const float*)d_in[0];
    const int*   ei  = (const int*)d_in[1];
    const float* W1  = (const float*)d_in[2];
    const float* al1 = (const float*)d_in[3];
    const float* ar1 = (const float*)d_in[4];
    const float* b1  = (const float*)d_in[5];
    const float* W2  = (const float*)d_in[6];
    const float* al2 = (const float*)d_in[7];
    const float* ar2 = (const float*)d_in[8];
    const float* b2  = (const float*)d_in[9];
    const float* W3  = (const float*)d_in[10];
    const float* al3 = (const float*)d_in[11];
    const float* ar3 = (const float*)d_in[12];
    const float* b3  = (const float*)d_in[13];
    const float* Wb  = (const float*)d_in[14];
    const float* bb  = (const float*)d_in[15];
    float* out = (float*)d_out;

    const int* src = ei;
    const int* dst = ei + Ee;

    const int SMEM_GEMM = 128 * WPAD * 4 + 128 * WPAD * 2;   // 69632 + 34816 = 104448 B -> 2 CTAs/SM
    cudaFuncSetAttribute(gemm_tf32_kernel, cudaFuncAttributeMaxDynamicSharedMemorySize, SMEM_GEMM);

    float *hm, *ha, *hb, *Tp;
    cudaGetSymbolAddress((void**)&hm, g_hm);
    cudaGetSymbolAddress((void**)&ha, g_ha);
    cudaGetSymbolAddress((void**)&hb, g_hb);
    cudaGetSymbolAddress((void**)&Tp, g_T);

    const int GEMM_GRID = 782;                 // 2 CTAs/SM now -> more, smaller waves
    const int AGG_GRID  = (Nn * 32 + 255) / 256;

    // Launch #4 = gemm1 (profiled slot); gemm1 independent of CSR kernels.
    zero_cnt_kernel<<<NB, 256>>>();                                              // 1
    hist_kernel<<<2048, 256>>>(dst);                                             // 2
    scanA_kernel<<<NB, 256>>>();                                                 // 3
    gemm_tf32_kernel<<<GEMM_GRID, 256, SMEM_GEMM>>>(x, W1, al1, ar1, hm, Nn, 1); // 4 (profiled)
    scanB_kernel<<<1, 256>>>();                                                  // 5
    scanC_kernel<<<NB, 256>>>();                                                 // 6
    scatter_kernel<<<2048, 256>>>(src, dst);                                     // 7

    // layer 1 aggregation
    agg_kernel<<<AGG_GRID, 256>>>(hm, b1, ha, 1);
    // layer 2
    gemm_tf32_kernel<<<GEMM_GRID, 256, SMEM_GEMM>>>(ha, W2, al2, ar2, hm, Nn, 1);
    agg_kernel<<<AGG_GRID, 256>>>(hm, b2, hb, 1);
    // layer 3
    gemm_tf32_kernel<<<GEMM_GRID, 256, SMEM_GEMM>>>(hb, W3, al3, ar3, hm, Nn, 1);
    agg_kernel<<<AGG_GRID, 256>>>(hm, b3, ha, 0);

    // bilinear head
    gemm_tf32_kernel<<<8, 256, SMEM_GEMM>>>(ha + (size_t)NUc * Hh, Wb, al1, ar1, Tp, NMc, 0);
    scores_kernel<<<512, 256>>>(Tp, ha + (size_t)(NUc + NMc) * Hh, bb, out);
}

// round 7
// speedup vs baseline: 1.3066x; 1.2012x over previous
#include <cuda_runtime.h>
#include <cuda_bf16.h>
#include <math.h>
#include <stdint.h>

#define Nn 50000
#define Ee 1600000
#define Hh 128
#define NUc 49232
#define NMc 512
#define NSc 256
#define NB 196   // ceil(Nn/256)

// ---------------- scratch (static device globals; no allocation) ----------------
__device__ float g_hm[(size_t)Nn * Hh];   // GEMM output (pre-aggregation), reused per layer
__device__ float g_ha[(size_t)Nn * Hh];   // ping (agg output)
__device__ float g_hb[(size_t)Nn * Hh];   // pong
__device__ float g_el[Nn];
__device__ float g_er[Nn];
__device__ int   g_cnt[Nn];
__device__ int   g_rowptr[Nn + 1];
__device__ int   g_cursor[Nn];
__device__ int   g_ssrc[Ee];
__device__ float g_T[NMc * Hh];
__device__ int   g_bsum[NB];
__device__ int   g_boff[NB];

// ---------------- CSR build ----------------
__global__ void zero_cnt_kernel() {
    int i = blockIdx.x * blockDim.x + threadIdx.x;
    if (i < Nn) g_cnt[i] = 0;
}

__global__ void hist_kernel(const int* __restrict__ dst) {
    int stride = gridDim.x * blockDim.x;
#pragma unroll 4
    for (int i = blockIdx.x * blockDim.x + threadIdx.x; i < Ee; i += stride)
        atomicAdd(&g_cnt[dst[i]], 1);
}

__global__ void scanA_kernel() {
    __shared__ int ws[8];
    int t = threadIdx.x, lane = t & 31, warp = t >> 5;
    int i = blockIdx.x * 256 + t;
    int v = (i < Nn) ? g_cnt[i] : 0;
    int x = v;
#pragma unroll
    for (int o = 16; o; o >>= 1) x += __shfl_xor_sync(0xffffffffu, x, o);
    if (lane == 0) ws[warp] = x;
    __syncthreads();
    if (t == 0) {
        int s = 0;
#pragma unroll
        for (int w = 0; w < 8; ++w) s += ws[w];
        g_bsum[blockIdx.x] = s;
    }
}

__global__ void scanB_kernel() {
    __shared__ int s[256];
    int t = threadIdx.x;
    s[t] = (t < NB) ? g_bsum[t] : 0;
    __syncthreads();
#pragma unroll
    for (int off = 1; off < 256; off <<= 1) {
        int v = (t >= off) ? s[t - off] : 0;
        __syncthreads();
        s[t] += v;
        __syncthreads();
    }
    if (t < NB) g_boff[t] = s[t] - g_bsum[t];
    if (t == 0) g_rowptr[Nn] = Ee;
}

__global__ void scanC_kernel() {
    __shared__ int s[256];
    int t = threadIdx.x;
    int i = blockIdx.x * 256 + t;
    int v = (i < Nn) ? g_cnt[i] : 0;
    s[t] = v;
    __syncthreads();
#pragma unroll
    for (int off = 1; off < 256; off <<= 1) {
        int q = (t >= off) ? s[t - off] : 0;
        __syncthreads();
        s[t] += q;
        __syncthreads();
    }
    if (i < Nn) {
        int excl = s[t] - v + g_boff[blockIdx.x];
        g_rowptr[i] = excl;
        g_cursor[i] = excl;
    }
}

__global__ void scatter_kernel(const int* __restrict__ src, const int* __restrict__ dst) {
    int stride = gridDim.x * blockDim.x;
#pragma unroll 4
    for (int i = blockIdx.x * blockDim.x + threadIdx.x; i < Ee; i += stride) {
        int d = dst[i];
        int p = atomicAdd(&g_cursor[d], 1);
        g_ssrc[p] = src[i];
    }
}

// ---------------- bf16 tensor-core GEMM, 2-term error-compensated split ----------------
// Hout = X @ W, fp32 in/out. x = xh+xl, w = wh+wl (bf16 each);
// D = xh*wh + xh*wl + xl*wh (xl*wl ~2^-18 dropped). fp32 accumulate.
__device__ __forceinline__ void mma_bf16(float c[4], uint32_t a0, uint32_t a1, uint32_t a2, uint32_t a3,
                                         uint32_t b0, uint32_t b1) {
    asm volatile(
        "mma.sync.aligned.m16n8k16.row.col.f32.bf16.bf16.f32 "
        "{%0,%1,%2,%3}, {%4,%5,%6,%7}, {%8,%9}, {%0,%1,%2,%3};"
        : "+f"(c[0]), "+f"(c[1]), "+f"(c[2]), "+f"(c[3])
        : "r"(a0), "r"(a1), "r"(a2), "r"(a3), "r"(b0), "r"(b1));
}

__device__ __forceinline__ void split_bf16x2(float x0, float x1, uint32_t& hi, uint32_t& lo) {
    __nv_bfloat162 h = __floats2bfloat162_rn(x0, x1);
    float2 hf = __bfloat1622float2(h);
    __nv_bfloat162 l = __floats2bfloat162_rn(x0 - hf.x, x1 - hf.y);
    hi = *(uint32_t*)&h;
    lo = *(uint32_t*)&l;
}

#define KPAD 136   // bf16 elements per row of transposed W tiles

__global__ __launch_bounds__(256, 2)
void gemm_bf16_kernel(const float* __restrict__ X, const float* __restrict__ W,
                      const float* __restrict__ al, const float* __restrict__ ar,
                      float* __restrict__ Hout, int nrows, int compute_elr) {
    extern __shared__ uint16_t smem16[];            // WhiT[128n][136k] | WloT[128n][136k], bf16 bits
    uint16_t* WhiT = smem16;
    uint16_t* WloT = smem16 + 128 * KPAD;

    // stage W transposed: WhiT[n][k] = bf16(W[k][n]); WloT = bf16(residual)
    for (int i = threadIdx.x; i < Hh * Hh; i += blockDim.x) {
        int k = i >> 7, n = i & 127;
        float w = W[i];
        __nv_bfloat16 hb = __float2bfloat16(w);
        float hf = __bfloat162float(hb);
        WhiT[n * KPAD + k] = *(uint16_t*)&hb;
        __nv_bfloat16 lb = __float2bfloat16(w - hf);
        WloT[n * KPAD + k] = *(uint16_t*)&lb;
    }
    __syncthreads();

    const unsigned FULL = 0xffffffffu;
    int lane = threadIdx.x & 31;
    int warp = threadIdx.x >> 5;
    int g = lane >> 2, tig = lane & 3;
    int gw = blockIdx.x * (blockDim.x >> 5) + warp;
    int nwarps = gridDim.x * (blockDim.x >> 5);
    int ngroups = (nrows + 15) >> 4;

    for (int grp = gw; grp < ngroups; grp += nwarps) {
        int row0 = grp * 16;
        int rA = row0 + g, rB = row0 + g + 8;
        bool vA = rA < nrows, vB = rB < nrows;

        float c[16][4];
#pragma unroll
        for (int nt = 0; nt < 16; ++nt) {
            c[nt][0] = 0.f; c[nt][1] = 0.f; c[nt][2] = 0.f; c[nt][3] = 0.f;
        }

#pragma unroll 2
        for (int kt = 0; kt < 8; ++kt) {
            int k0 = kt * 16;
            float2 z2 = make_float2(0.f, 0.f);
            float2 xa0 = vA ? *(const float2*)(X + (size_t)rA * Hh + k0 + 2 * tig)     : z2;
            float2 xa1 = vA ? *(const float2*)(X + (size_t)rA * Hh + k0 + 2 * tig + 8) : z2;
            float2 xb0 = vB ? *(const float2*)(X + (size_t)rB * Hh + k0 + 2 * tig)     : z2;
            float2 xb1 = vB ? *(const float2*)(X + (size_t)rB * Hh + k0 + 2 * tig + 8) : z2;

            uint32_t ahi[4], alo[4];
            split_bf16x2(xa0.x, xa0.y, ahi[0], alo[0]);   // row g,   k 2t..2t+1
            split_bf16x2(xb0.x, xb0.y, ahi[1], alo[1]);   // row g+8, k 2t..2t+1
            split_bf16x2(xa1.x, xa1.y, ahi[2], alo[2]);   // row g,   k 2t+8..
            split_bf16x2(xb1.x, xb1.y, ahi[3], alo[3]);   // row g+8, k 2t+8..

#pragma unroll
            for (int nt = 0; nt < 16; ++nt) {
                int n = nt * 8 + g;
                int base = n * KPAD + k0 + 2 * tig;       // even index -> 4B aligned
                uint32_t bh0 = *(const uint32_t*)&WhiT[base];
                uint32_t bh1 = *(const uint32_t*)&WhiT[base + 8];
                uint32_t bl0 = *(const uint32_t*)&WloT[base];
                uint32_t bl1 = *(const uint32_t*)&WloT[base + 8];
                mma_bf16(c[nt], ahi[0], ahi[1], ahi[2], ahi[3], bh0, bh1);  // hi*hi
                mma_bf16(c[nt], ahi[0], ahi[1], ahi[2], ahi[3], bl0, bl1);  // hi*lo
                mma_bf16(c[nt], alo[0], alo[1], alo[2], alo[3], bh0, bh1);  // lo*hi
            }
        }

        float pal = 0.f, par = 0.f, pbl = 0.f, pbr = 0.f;
#pragma unroll
        for (int nt = 0; nt < 16; ++nt) {
            int col = nt * 8 + 2 * tig;
            if (vA) *(float2*)&Hout[(size_t)rA * Hh + col] = make_float2(c[nt][0], c[nt][1]);
            if (vB) *(float2*)&Hout[(size_t)rB * Hh + col] = make_float2(c[nt][2], c[nt][3]);
            if (compute_elr) {
                float a0 = al[col], a1 = al[col + 1];
                float r0v = ar[col], r1v = ar[col + 1];
                pal += c[nt][0] * a0 + c[nt][1] * a1;
                par += c[nt][0] * r0v + c[nt][1] * r1v;
                pbl += c[nt][2] * a0 + c[nt][3] * a1;
                pbr += c[nt][2] * r0v + c[nt][3] * r1v;
            }
        }
        if (compute_elr) {
#pragma unroll
            for (int o = 1; o < 4; o <<= 1) {
                pal += __shfl_xor_sync(FULL, pal, o);
                par += __shfl_xor_sync(FULL, par, o);
                pbl += __shfl_xor_sync(FULL, pbl, o);
                pbr += __shfl_xor_sync(FULL, pbr, o);
            }
            if (tig == 0) {
                if (vA) { g_el[rA] = pal; g_er[rA] = par; }
                if (vB) { g_el[rB] = pbl; g_er[rB] = pbr; }
            }
        }
    }
}

// ---------------- fused edge softmax + aggregation (round-3 form: warp per node) ----------------
__global__ void agg_kernel(const float* __restrict__ h, const float* __restrict__ bias,
                           float* __restrict__ hout, int do_relu) {
    int lane = threadIdx.x & 31;
    int v = (blockIdx.x * blockDim.x + threadIdx.x) >> 5;
    if (v >= Nn) return;

    int r0 = g_rowptr[v];
    int r1 = g_rowptr[v + 1];
    float elv = g_el[v];

    float4 acc = make_float4(0.f, 0.f, 0.f, 0.f);
    float s = 0.f;
#pragma unroll 4
    for (int i = r0; i < r1; ++i) {
        int sv = g_ssrc[i];
        float e = elv + g_er[sv];
        e = e > 0.f ? e : 0.2f * e;
        float w = __expf(e);
        s += w;
        float4 hv = *(const float4*)(h + (size_t)sv * Hh + lane * 4);
        acc.x += w * hv.x;
        acc.y += w * hv.y;
        acc.z += w * hv.z;
        acc.w += w * hv.w;
    }

    float inv = 1.f / (s + 1e-10f);
    float4 bv = *(const float4*)(bias + lane * 4);
    float4 o;
    o.x = acc.x * inv + bv.x;
    o.y = acc.y * inv + bv.y;
    o.z = acc.z * inv + bv.z;
    o.w = acc.w * inv + bv.w;
    if (do_relu) {
        o.x = fmaxf(o.x, 0.f);
        o.y = fmaxf(o.y, 0.f);
        o.z = fmaxf(o.z, 0.f);
        o.w = fmaxf(o.w, 0.f);
    }
    *(float4*)(hout + (size_t)v * Hh + lane * 4) = o;
}

// ---------------- scores = T @ server^T + bb ----------------
__global__ void scores_kernel(const float* __restrict__ Tm, const float* __restrict__ S,
                              const float* __restrict__ bb, float* __restrict__ out) {
    const unsigned FULL = 0xffffffffu;
    int lane = threadIdx.x & 31;
    int w = (blockIdx.x * blockDim.x + threadIdx.x) >> 5;
    if (w >= NMc * 8) return;
    int m = w >> 3;
    int sbase = (w & 7) * 32;
    float4 t = ((const float4*)(Tm + (size_t)m * Hh))[lane];
    float b = bb[0];
    for (int j = 0; j < 32; ++j) {
        int sidx = sbase + j;
        float4 sv = ((const float4*)(S + (size_t)sidx * Hh))[lane];
        float d = t.x * sv.x + t.y * sv.y + t.z * sv.z + t.w * sv.w;
#pragma unroll
        for (int o = 16; o; o >>= 1) d += __shfl_xor_sync(FULL, d, o);
        if (lane == 0) out[m * NSc + sidx] = d + b;
    }
}

// ---------------- launch ----------------
extern "C" void kernel_launch(void* const* d_in, const int* in_sizes, int n_in,
                              void* d_out, int out_size) {
    (void)in_sizes; (void)n_in; (void)out_size;
    const float* x   = (const float*)d_in[0];
    const int*   ei  = (const int*)d_in[1];
    const float* W1  = (const float*)d_in[2];
    const float* al1 = (const float*)d_in[3];
    const float* ar1 = (const float*)d_in[4];
    const float* b1  = (const float*)d_in[5];
    const float* W2  = (const float*)d_in[6];
    const float* al2 = (const float*)d_in[7];
    const float* ar2 = (const float*)d_in[8];
    const float* b2  = (const float*)d_in[9];
    const float* W3  = (const float*)d_in[10];
    const float* al3 = (const float*)d_in[11];
    const float* ar3 = (const float*)d_in[12];
    const float* b3  = (const float*)d_in[13];
    const float* Wb  = (const float*)d_in[14];
    const float* bb  = (const float*)d_in[15];
    float* out = (float*)d_out;

    const int* src = ei;
    const int* dst = ei + Ee;

    const int SMEM_GEMM = 2 * 128 * KPAD * 2;   // 69632 B -> 2 CTAs/SM
    cudaFuncSetAttribute(gemm_bf16_kernel, cudaFuncAttributeMaxDynamicSharedMemorySize, SMEM_GEMM);

    float *hm, *ha, *hb, *Tp;
    cudaGetSymbolAddress((void**)&hm, g_hm);
    cudaGetSymbolAddress((void**)&ha, g_ha);
    cudaGetSymbolAddress((void**)&hb, g_hb);
    cudaGetSymbolAddress((void**)&Tp, g_T);

    const int GEMM_GRID = 782;
    const int AGG_GRID  = (Nn * 32 + 255) / 256;

    // Launch #4 = gemm1 (profiled slot); gemm1 independent of CSR kernels.
    zero_cnt_kernel<<<NB, 256>>>();                                              // 1
    hist_kernel<<<2048, 256>>>(dst);                                             // 2
    scanA_kernel<<<NB, 256>>>();                                                 // 3
    gemm_bf16_kernel<<<GEMM_GRID, 256, SMEM_GEMM>>>(x, W1, al1, ar1, hm, Nn, 1); // 4 (profiled)
    scanB_kernel<<<1, 256>>>();                                                  // 5
    scanC_kernel<<<NB, 256>>>();                                                 // 6
    scatter_kernel<<<2048, 256>>>(src, dst);                                     // 7

    // layer 1 aggregation
    agg_kernel<<<AGG_GRID, 256>>>(hm, b1, ha, 1);
    // layer 2
    gemm_bf16_kernel<<<GEMM_GRID, 256, SMEM_GEMM>>>(ha, W2, al2, ar2, hm, Nn, 1);
    agg_kernel<<<AGG_GRID, 256>>>(hm, b2, hb, 1);
    // layer 3
    gemm_bf16_kernel<<<GEMM_GRID, 256, SMEM_GEMM>>>(hb, W3, al3, ar3, hm, Nn, 1);
    agg_kernel<<<AGG_GRID, 256>>>(hm, b3, ha, 0);

    // bilinear head
    gemm_bf16_kernel<<<8, 256, SMEM_GEMM>>>(ha + (size_t)NUc * Hh, Wb, al1, ar1, Tp, NMc, 0);
    scores_kernel<<<512, 256>>>(Tp, ha + (size_t)(NUc + NMc) * Hh, bb, out);
}

// round 8
// speedup vs baseline: 1.4338x; 1.0974x over previous
#include <cuda_runtime.h>
#include <cuda_bf16.h>
#include <math.h>
#include <stdint.h>

#define Nn 50000
#define Ee 1600000
#define Hh 128
#define NUc 49232
#define NMc 512
#define NSc 256
#define NB 196   // ceil(Nn/256)

// ---------------- scratch (static device globals; no allocation) ----------------
__device__ float g_hm[(size_t)Nn * Hh];   // GEMM output (pre-aggregation), reused per layer
__device__ float g_ha[(size_t)Nn * Hh];   // ping (agg output)
__device__ float g_hb[(size_t)Nn * Hh];   // pong
__device__ float g_el[Nn];
__device__ float g_er[Nn];
__device__ int   g_cnt[Nn];
__device__ int   g_rowptr[Nn + 1];
__device__ int   g_cursor[Nn];
__device__ int   g_ssrc[Ee];
__device__ float g_T[NMc * Hh];
__device__ int   g_bsum[NB];
__device__ int   g_boff[NB];

// ---------------- CSR build ----------------
__global__ void zero_cnt_kernel() {
    int i = blockIdx.x * blockDim.x + threadIdx.x;
    if (i < Nn) g_cnt[i] = 0;
}

__global__ void hist_kernel(const int* __restrict__ dst) {
    int stride = gridDim.x * blockDim.x;
#pragma unroll 4
    for (int i = blockIdx.x * blockDim.x + threadIdx.x; i < Ee; i += stride)
        atomicAdd(&g_cnt[dst[i]], 1);
}

__global__ void scanA_kernel() {
    __shared__ int ws[8];
    int t = threadIdx.x, lane = t & 31, warp = t >> 5;
    int i = blockIdx.x * 256 + t;
    int v = (i < Nn) ? g_cnt[i] : 0;
    int x = v;
#pragma unroll
    for (int o = 16; o; o >>= 1) x += __shfl_xor_sync(0xffffffffu, x, o);
    if (lane == 0) ws[warp] = x;
    __syncthreads();
    if (t == 0) {
        int s = 0;
#pragma unroll
        for (int w = 0; w < 8; ++w) s += ws[w];
        g_bsum[blockIdx.x] = s;
    }
}

__global__ void scanB_kernel() {
    __shared__ int s[256];
    int t = threadIdx.x;
    s[t] = (t < NB) ? g_bsum[t] : 0;
    __syncthreads();
#pragma unroll
    for (int off = 1; off < 256; off <<= 1) {
        int v = (t >= off) ? s[t - off] : 0;
        __syncthreads();
        s[t] += v;
        __syncthreads();
    }
    if (t < NB) g_boff[t] = s[t] - g_bsum[t];
    if (t == 0) g_rowptr[Nn] = Ee;
}

__global__ void scanC_kernel() {
    __shared__ int s[256];
    int t = threadIdx.x;
    int i = blockIdx.x * 256 + t;
    int v = (i < Nn) ? g_cnt[i] : 0;
    s[t] = v;
    __syncthreads();
#pragma unroll
    for (int off = 1; off < 256; off <<= 1) {
        int q = (t >= off) ? s[t - off] : 0;
        __syncthreads();
        s[t] += q;
        __syncthreads();
    }
    if (i < Nn) {
        int excl = s[t] - v + g_boff[blockIdx.x];
        g_rowptr[i] = excl;
        g_cursor[i] = excl;
    }
}

__global__ void scatter_kernel(const int* __restrict__ src, const int* __restrict__ dst) {
    int stride = gridDim.x * blockDim.x;
#pragma unroll 4
    for (int i = blockIdx.x * blockDim.x + threadIdx.x; i < Ee; i += stride) {
        int d = dst[i];
        int p = atomicAdd(&g_cursor[d], 1);
        g_ssrc[p] = src[i];
    }
}

// ---------------- bf16 tensor-core GEMM, 2-term split, packed uint4 B fragments ----------------
// Hout = X @ W, fp32 in/out. x = xh+xl, w = wh+wl (bf16 each);
// D = xh*wh + xh*wl + xl*wh (xl*wl ~2^-18 dropped). fp32 accumulate.
// Smem: Wp[n][kt][tig] = uint4{bh0, bh1, bl0, bl1}; per-n stride 36 uint4 (bank-conflict-free).
__device__ __forceinline__ void mma_bf16(float c[4], uint32_t a0, uint32_t a1, uint32_t a2, uint32_t a3,
                                         uint32_t b0, uint32_t b1) {
    asm volatile(
        "mma.sync.aligned.m16n8k16.row.col.f32.bf16.bf16.f32 "
        "{%0,%1,%2,%3}, {%4,%5,%6,%7}, {%8,%9}, {%0,%1,%2,%3};"
        : "+f"(c[0]), "+f"(c[1]), "+f"(c[2]), "+f"(c[3])
        : "r"(a0), "r"(a1), "r"(a2), "r"(a3), "r"(b0), "r"(b1));
}

__device__ __forceinline__ void split_bf16x2(float x0, float x1, uint32_t& hi, uint32_t& lo) {
    __nv_bfloat162 h = __floats2bfloat162_rn(x0, x1);
    float2 hf = __bfloat1622float2(h);
    __nv_bfloat162 l = __floats2bfloat162_rn(x0 - hf.x, x1 - hf.y);
    hi = *(uint32_t*)&h;
    lo = *(uint32_t*)&l;
}

#define NSTRIDE 36   // uint4s per n row (32 data + 4 pad -> bank shift of 16 per n)

__global__ __launch_bounds__(256, 2)
void gemm_bf16_kernel(const float* __restrict__ X, const float* __restrict__ W,
                      const float* __restrict__ al, const float* __restrict__ ar,
                      float* __restrict__ Hout, int nrows, int compute_elr) {
    extern __shared__ uint4 Wp[];   // [128][NSTRIDE]

    // stage W: for each (n, kt, tig) pack {bh0, bh1, bl0, bl1}
    for (int i = threadIdx.x; i < 4096; i += blockDim.x) {
        int n = i & 127;
        int r = i >> 7;              // 0..31
        int kt = r >> 2, tig = r & 3;
        int k0 = kt * 16 + 2 * tig;
        float w00 = W[(size_t)k0 * Hh + n];
        float w01 = W[(size_t)(k0 + 1) * Hh + n];
        float w10 = W[(size_t)(k0 + 8) * Hh + n];
        float w11 = W[(size_t)(k0 + 9) * Hh + n];
        uint4 v;
        split_bf16x2(w00, w01, v.x, v.z);
        split_bf16x2(w10, w11, v.y, v.w);
        Wp[n * NSTRIDE + kt * 4 + tig] = v;
    }
    __syncthreads();

    const unsigned FULL = 0xffffffffu;
    int lane = threadIdx.x & 31;
    int warp = threadIdx.x >> 5;
    int g = lane >> 2, tig = lane & 3;
    int gw = blockIdx.x * (blockDim.x >> 5) + warp;
    int nwarps = gridDim.x * (blockDim.x >> 5);
    int ngroups = (nrows + 15) >> 4;

    for (int grp = gw; grp < ngroups; grp += nwarps) {
        int row0 = grp * 16;
        int rA = row0 + g, rB = row0 + g + 8;
        bool vA = rA < nrows, vB = rB < nrows;

        float c[16][4];
#pragma unroll
        for (int nt = 0; nt < 16; ++nt) {
            c[nt][0] = 0.f; c[nt][1] = 0.f; c[nt][2] = 0.f; c[nt][3] = 0.f;
        }

#pragma unroll 2
        for (int kt = 0; kt < 8; ++kt) {
            int k0 = kt * 16;
            float2 z2 = make_float2(0.f, 0.f);
            float2 xa0 = vA ? *(const float2*)(X + (size_t)rA * Hh + k0 + 2 * tig)     : z2;
            float2 xa1 = vA ? *(const float2*)(X + (size_t)rA * Hh + k0 + 2 * tig + 8) : z2;
            float2 xb0 = vB ? *(const float2*)(X + (size_t)rB * Hh + k0 + 2 * tig)     : z2;
            float2 xb1 = vB ? *(const float2*)(X + (size_t)rB * Hh + k0 + 2 * tig + 8) : z2;

            uint32_t ahi[4], alo[4];
            split_bf16x2(xa0.x, xa0.y, ahi[0], alo[0]);
            split_bf16x2(xb0.x, xb0.y, ahi[1], alo[1]);
            split_bf16x2(xa1.x, xa1.y, ahi[2], alo[2]);
            split_bf16x2(xb1.x, xb1.y, ahi[3], alo[3]);

            const uint4* wrow = Wp + (size_t)kt * 4 + tig;
#pragma unroll
            for (int nt = 0; nt < 16; ++nt) {
                int n = nt * 8 + g;
                uint4 b = wrow[n * NSTRIDE];
                mma_bf16(c[nt], ahi[0], ahi[1], ahi[2], ahi[3], b.x, b.y);  // hi*hi
                mma_bf16(c[nt], ahi[0], ahi[1], ahi[2], ahi[3], b.z, b.w);  // hi*lo
                mma_bf16(c[nt], alo[0], alo[1], alo[2], alo[3], b.x, b.y);  // lo*hi
            }
        }

        float pal = 0.f, par = 0.f, pbl = 0.f, pbr = 0.f;
#pragma unroll
        for (int nt = 0; nt < 16; ++nt) {
            int col = nt * 8 + 2 * tig;
            if (vA) *(float2*)&Hout[(size_t)rA * Hh + col] = make_float2(c[nt][0], c[nt][1]);
            if (vB) *(float2*)&Hout[(size_t)rB * Hh + col] = make_float2(c[nt][2], c[nt][3]);
            if (compute_elr) {
                float a0 = al[col], a1 = al[col + 1];
                float r0v = ar[col], r1v = ar[col + 1];
                pal += c[nt][0] * a0 + c[nt][1] * a1;
                par += c[nt][0] * r0v + c[nt][1] * r1v;
                pbl += c[nt][2] * a0 + c[nt][3] * a1;
                pbr += c[nt][2] * r0v + c[nt][3] * r1v;
            }
        }
        if (compute_elr) {
#pragma unroll
            for (int o = 1; o < 4; o <<= 1) {
                pal += __shfl_xor_sync(FULL, pal, o);
                par += __shfl_xor_sync(FULL, par, o);
                pbl += __shfl_xor_sync(FULL, pbl, o);
                pbr += __shfl_xor_sync(FULL, pbr, o);
            }
            if (tig == 0) {
                if (vA) { g_el[rA] = pal; g_er[rA] = par; }
                if (vB) { g_el[rB] = pbl; g_er[rB] = pbr; }
            }
        }
    }
}

// ---------------- fused edge softmax + aggregation (warp per node) ----------------
__global__ void agg_kernel(const float* __restrict__ h, const float* __restrict__ bias,
                           float* __restrict__ hout, int do_relu) {
    int lane = threadIdx.x & 31;
    int v = (blockIdx.x * blockDim.x + threadIdx.x) >> 5;
    if (v >= Nn) return;

    int r0 = g_rowptr[v];
    int r1 = g_rowptr[v + 1];
    float elv = g_el[v];

    float4 acc = make_float4(0.f, 0.f, 0.f, 0.f);
    float s = 0.f;
#pragma unroll 4
    for (int i = r0; i < r1; ++i) {
        int sv = g_ssrc[i];
        float e = elv + g_er[sv];
        e = e > 0.f ? e : 0.2f * e;
        float w = __expf(e);
        s += w;
        float4 hv = *(const float4*)(h + (size_t)sv * Hh + lane * 4);
        acc.x += w * hv.x;
        acc.y += w * hv.y;
        acc.z += w * hv.z;
        acc.w += w * hv.w;
    }

    float inv = 1.f / (s + 1e-10f);
    float4 bv = *(const float4*)(bias + lane * 4);
    float4 o;
    o.x = acc.x * inv + bv.x;
    o.y = acc.y * inv + bv.y;
    o.z = acc.z * inv + bv.z;
    o.w = acc.w * inv + bv.w;
    if (do_relu) {
        o.x = fmaxf(o.x, 0.f);
        o.y = fmaxf(o.y, 0.f);
        o.z = fmaxf(o.z, 0.f);
        o.w = fmaxf(o.w, 0.f);
    }
    *(float4*)(hout + (size_t)v * Hh + lane * 4) = o;
}

// ---------------- scores = T @ server^T + bb ----------------
__global__ void scores_kernel(const float* __restrict__ Tm, const float* __restrict__ S,
                              const float* __restrict__ bb, float* __restrict__ out) {
    const unsigned FULL = 0xffffffffu;
    int lane = threadIdx.x & 31;
    int w = (blockIdx.x * blockDim.x + threadIdx.x) >> 5;
    if (w >= NMc * 8) return;
    int m = w >> 3;
    int sbase = (w & 7) * 32;
    float4 t = ((const float4*)(Tm + (size_t)m * Hh))[lane];
    float b = bb[0];
    for (int j = 0; j < 32; ++j) {
        int sidx = sbase + j;
        float4 sv = ((const float4*)(S + (size_t)sidx * Hh))[lane];
        float d = t.x * sv.x + t.y * sv.y + t.z * sv.z + t.w * sv.w;
#pragma unroll
        for (int o = 16; o; o >>= 1) d += __shfl_xor_sync(FULL, d, o);
        if (lane == 0) out[m * NSc + sidx] = d + b;
    }
}

// ---------------- launch ----------------
extern "C" void kernel_launch(void* const* d_in, const int* in_sizes, int n_in,
                              void* d_out, int out_size) {
    (void)in_sizes; (void)n_in; (void)out_size;
    const float* x   = (const float*)d_in[0];
    const int*   ei  = (const int*)d_in[1];
    const float* W1  = (const float*)d_in[2];
    const float* al1 = (const float*)d_in[3];
    const float* ar1 = (const float*)d_in[4];
    const float* b1  = (const float*)d_in[5];
    const float* W2  = (const float*)d_in[6];
    const float* al2 = (const float*)d_in[7];
    const float* ar2 = (const float*)d_in[8];
    const float* b2  = (const float*)d_in[9];
    const float* W3  = (const float*)d_in[10];
    const float* al3 = (const float*)d_in[11];
    const float* ar3 = (const float*)d_in[12];
    const float* b3  = (const float*)d_in[13];
    const float* Wb  = (const float*)d_in[14];
    const float* bb  = (const float*)d_in[15];
    float* out = (float*)d_out;

    const int* src = ei;
    const int* dst = ei + Ee;

    const int SMEM_GEMM = 128 * NSTRIDE * 16;   // 73728 B -> 2 CTAs/SM
    cudaFuncSetAttribute(gemm_bf16_kernel, cudaFuncAttributeMaxDynamicSharedMemorySize, SMEM_GEMM);

    float *hm, *ha, *hb, *Tp;
    cudaGetSymbolAddress((void**)&hm, g_hm);
    cudaGetSymbolAddress((void**)&ha, g_ha);
    cudaGetSymbolAddress((void**)&hb, g_hb);
    cudaGetSymbolAddress((void**)&Tp, g_T);

    const int GEMM_GRID = 391;                  // 3128 warps vs 3125 row-groups
    const int AGG_GRID  = (Nn * 32 + 255) / 256;

    // Launch #4 = gemm1 (profiled slot); gemm1 independent of CSR kernels.
    zero_cnt_kernel<<<NB, 256>>>();                                              // 1
    hist_kernel<<<2048, 256>>>(dst);                                             // 2
    scanA_kernel<<<NB, 256>>>();                                                 // 3
    gemm_bf16_kernel<<<GEMM_GRID, 256, SMEM_GEMM>>>(x, W1, al1, ar1, hm, Nn, 1); // 4 (profiled)
    scanB_kernel<<<1, 256>>>();                                                  // 5
    scanC_kernel<<<NB, 256>>>();                                                 // 6
    scatter_kernel<<<2048, 256>>>(src, dst);                                     // 7

    // layer 1 aggregation
    agg_kernel<<<AGG_GRID, 256>>>(hm, b1, ha, 1);
    // layer 2
    gemm_bf16_kernel<<<GEMM_GRID, 256, SMEM_GEMM>>>(ha, W2, al2, ar2, hm, Nn, 1);
    agg_kernel<<<AGG_GRID, 256>>>(hm, b2, hb, 1);
    // layer 3
    gemm_bf16_kernel<<<GEMM_GRID, 256, SMEM_GEMM>>>(hb, W3, al3, ar3, hm, Nn, 1);
    agg_kernel<<<AGG_GRID, 256>>>(hm, b3, ha, 0);

    // bilinear head
    gemm_bf16_kernel<<<8, 256, SMEM_GEMM>>>(ha + (size_t)NUc * Hh, Wb, al1, ar1, Tp, NMc, 0);
    scores_kernel<<<512, 256>>>(Tp, ha + (size_t)(NUc + NMc) * Hh, bb, out);
}